// round 9
// baseline (speedup 1.0000x reference)
#include <cuda_runtime.h>
#include <cuda_bf16.h>
#include <cstdint>

#define BATCH  131072
#define FEAT   32
#define DEG    16
#define CLS    64
#define GRIDK  8
#define TBR    64                  // rows per block
#define NBLK   (BATCH / TBR)       // 2048
#define GRID   148                 // persistent CTAs (1 per SM on B200)
#define NKT    16                  // K=256 / 16 per MMA

// ---- dynamic smem byte offsets ----
#define OFF_FLAG    0
#define OFF_PAR     64
#define PAR_WT      0              // [d][f] 512 floats
#define PAR_INV     512
#define PAR_CP      544
#define PAR_SP      560
#define PAR_SC      576
#define PAR_BI      608
#define PAR_KB      640
#define OFF_ABUF    4096           // 2 buffers x (A_HI 32KB + A_LO 32KB)
#define ABUF_STRIDE 65536
#define OFF_B_HI    (OFF_ABUF + 2 * ABUF_STRIDE)   // 135168
#define OFF_B_LO    (OFF_B_HI + 32768)
#define SMEM_TOTAL  (OFF_B_LO + 32768)             // 200704 B

static __device__ __forceinline__ uint32_t smem_u32(const void* p) {
    uint32_t a;
    asm("{ .reg .u64 t; cvta.to.shared.u64 t, %1; cvt.u32.u64 %0, t; }" : "=r"(a) : "l"(p));
    return a;
}
static __device__ __forceinline__ void ldsm4(uint32_t& r0, uint32_t& r1, uint32_t& r2,
                                             uint32_t& r3, uint32_t addr) {
    asm volatile("ldmatrix.sync.aligned.m8n8.x4.shared.b16 {%0,%1,%2,%3}, [%4];"
                 : "=r"(r0), "=r"(r1), "=r"(r2), "=r"(r3) : "r"(addr));
}
static __device__ __forceinline__ void mma_bf16(float* c, const uint32_t* a,
                                                const uint32_t* b) {
    asm volatile("mma.sync.aligned.m16n8k16.row.col.f32.bf16.bf16.f32 "
                 "{%0,%1,%2,%3}, {%4,%5,%6,%7}, {%8,%9}, {%0,%1,%2,%3};"
                 : "+f"(c[0]), "+f"(c[1]), "+f"(c[2]), "+f"(c[3])
                 : "r"(a[0]), "r"(a[1]), "r"(a[2]), "r"(a[3]), "r"(b[0]), "r"(b[1]));
}
static __device__ __forceinline__ uint32_t pack_bf2(float a, float b) {
    __nv_bfloat162 h = __floats2bfloat162_rn(a, b);
    return *reinterpret_cast<uint32_t*>(&h);
}

// ---- producer: stage-1 (verified R4 math) + Chebyshev basis -> A hi/lo tiles ----
static __device__ __forceinline__ void produce_block(
    char* smc, const float* __restrict__ X, const float* par,
    int blk, int buf, int pt /*0..127*/) {
    const float CLIPF = (float)(1.0 - 1e-6);
    const int f  = pt & 31;
    const int w8 = pt >> 5;          // 0..3
    const int row0 = blk * TBR;
    char* aHi = smc + OFF_ABUF + buf * ABUF_STRIDE;
    char* aLo = aHi + 32768;
    const float invd = par[PAR_INV + f];
    const float sc   = par[PAR_SC + f];
    const float bi   = par[PAR_BI + f];
#pragma unroll 2
    for (int i = 0; i < TBR / 4; i++) {
        const int r = w8 * 16 + i;
        float x = X[(size_t)(row0 + r) * FEAT + f];
        x = fminf(fmaxf(x, -CLIPF), CLIPF);
        const float sn = sqrtf(fmaf(-x, x, 1.0f));
        float c = x, s = sn, num = 0.f;
#pragma unroll
        for (int d = 0; d < DEG; d++) {
            const float q = fmaf(c, par[PAR_CP + d], -(s * par[PAR_SP + d]));
            num = fmaf(par[PAR_WT + d * 32 + f], q, num);
            const float cn = fmaf(-sn, s, c * x);
            s = fmaf(sn, c, s * x);
            c = cn;
        }
        float y = tanhf(fmaf(sc, num * invd, bi));
        y = fminf(fmaxf(y, -CLIPF), CLIPF);

        float T[GRIDK];
        T[0] = 1.0f; T[1] = y;
        const float y2 = y + y;
#pragma unroll
        for (int k = 2; k < GRIDK; k++) T[k] = fmaf(y2, T[k - 1], -T[k - 2]);

        uint32_t hi[4], lo[4];
#pragma unroll
        for (int k = 0; k < 4; k++) {
            const __nv_bfloat16 h0 = __float2bfloat16_rn(T[2 * k]);
            const __nv_bfloat16 h1 = __float2bfloat16_rn(T[2 * k + 1]);
            const float l0 = T[2 * k]     - __bfloat162float(h0);
            const float l1 = T[2 * k + 1] - __bfloat162float(h1);
            __nv_bfloat162 hh; hh.x = h0; hh.y = h1;
            hi[k] = *reinterpret_cast<uint32_t*>(&hh);
            lo[k] = pack_bf2(l0, l1);
        }
        const uint32_t off = (uint32_t)(r * 512 + ((f ^ (r & 7)) << 4));
        *(uint4*)(aHi + off) = make_uint4(hi[0], hi[1], hi[2], hi[3]);
        *(uint4*)(aLo + off) = make_uint4(lo[0], lo[1], lo[2], lo[3]);
    }
}

// ---- consumer: MMA (R7-verified fragment mapping) + epilogue ----
static __device__ __forceinline__ void consume_block(
    uint32_t smem_base, const float* par, float* __restrict__ out,
    int blk, int buf, int cw /*0..3*/, int lane) {
    const int lr = lane & 7;
    const int a_cb = (lane >> 4) & 1;
    const int arow = cw * 16 + ((lane >> 3) & 1) * 8 + lr;
    const int b_cb = (lane >> 3) & 1;
    const int bn   = ((lane >> 4) & 1) * 8 + lr;

    const uint32_t aBufBase = smem_base + OFF_ABUF + buf * ABUF_STRIDE;
    const uint32_t aBaseHi = aBufBase + arow * 512;
    const uint32_t aBaseLo = aBaseHi + 32768u;
    uint32_t bBaseHi[4];
#pragma unroll
    for (int p = 0; p < 4; p++)
        bBaseHi[p] = smem_base + OFF_B_HI + (p * 16 + bn) * 512;

    float C[8][4];
#pragma unroll
    for (int n = 0; n < 8; n++)
#pragma unroll
        for (int j = 0; j < 4; j++) C[n][j] = 0.f;

#pragma unroll
    for (int kt = 0; kt < NKT; kt++) {
        const uint32_t offA = (uint32_t)(((kt * 2 + a_cb) ^ lr) << 4);
        const uint32_t offB = (uint32_t)(((kt * 2 + b_cb) ^ lr) << 4);
        uint32_t ah[4], al[4];
        ldsm4(ah[0], ah[1], ah[2], ah[3], aBaseHi + offA);
        ldsm4(al[0], al[1], al[2], al[3], aBaseLo + offA);
        uint32_t bh[8][2], bl[8][2];
#pragma unroll
        for (int p = 0; p < 4; p++) {
            ldsm4(bh[2 * p][0], bh[2 * p][1], bh[2 * p + 1][0], bh[2 * p + 1][1],
                  bBaseHi[p] + offB);
            ldsm4(bl[2 * p][0], bl[2 * p][1], bl[2 * p + 1][0], bl[2 * p + 1][1],
                  bBaseHi[p] + 32768u + offB);
        }
#pragma unroll
        for (int n = 0; n < 8; n++) {
            mma_bf16(C[n], ah, bh[n]);
            mma_bf16(C[n], al, bh[n]);
            mma_bf16(C[n], ah, bl[n]);
        }
    }

    const int qrow = lane >> 2;
    const int col2 = 2 * (lane & 3);
    const int gr0 = blk * TBR + cw * 16 + qrow;
#pragma unroll
    for (int n = 0; n < 8; n++) {
        const int col = n * 8 + col2;
        const float kb0 = par[PAR_KB + col];
        const float kb1 = par[PAR_KB + col + 1];
        float2 v0, v1;
        v0.x = C[n][0] + kb0; v0.y = C[n][1] + kb1;
        v1.x = C[n][2] + kb0; v1.y = C[n][3] + kb1;
        *(float2*)(out + (size_t)gr0 * CLS + col) = v0;
        *(float2*)(out + (size_t)(gr0 + 8) * CLS + col) = v1;
    }
}

__global__ __launch_bounds__(256)
void qkan_pipe_kernel(const float* __restrict__ X,
                      const float* __restrict__ phases,
                      const float* __restrict__ lcu_w,
                      const float* __restrict__ cand0,
                      const float* __restrict__ cand1,
                      const float* __restrict__ kan_coeff,
                      const float* __restrict__ kan_bias,
                      float* __restrict__ out) {
    extern __shared__ char smc[];
    float* par = (float*)(smc + OFF_PAR);

    const int t    = threadIdx.x;
    const int wid  = t >> 5;
    const int lane = t & 31;
    const int bid  = blockIdx.x;
    const uint32_t smem_base = smem_u32(smc);

    // ---- scale/bias disambiguation (scale mean ~1 > bias mean ~0) ----
    if (t == 0) {
        float s0 = 0.f, s1 = 0.f;
        for (int i = 0; i < 32; i++) { s0 += cand0[i]; s1 += cand1[i]; }
        *(int*)(smc + OFF_FLAG) = (s0 > s1) ? 1 : 0;
    }
    __syncthreads();
    const int flag = *(const int*)(smc + OFF_FLAG);

    // ---- parameter staging (written cooperatively by ALL warps) ----
    for (int j = t; j < DEG * FEAT; j += 256) {        // lcu_w [f][d] -> wT [d][f]
        const int f = j >> 4, d = j & 15;
        par[PAR_WT + d * 32 + f] = lcu_w[j];
    }
    if (t < 32) {
        float denom = 1e-6f;
#pragma unroll
        for (int d = 0; d < DEG; d++) denom += fabsf(lcu_w[t * DEG + d]);
        par[PAR_INV + t] = 1.0f / denom;
        par[PAR_SC + t] = flag ? cand0[t] : cand1[t];
        par[PAR_BI + t] = flag ? cand1[t] : cand0[t];
    }
    if (t < 16) {
        float sv, cv;
        sincosf(phases[t], &sv, &cv);
        par[PAR_CP + t] = cv;
        par[PAR_SP + t] = sv;
    }
    if (t < 64) par[PAR_KB + t] = kan_bias[t];

    // ---- B tiles: kan_coeff [c][256] -> bf16 hi/lo, 512B rows, chunk^(c&7) swizzle ----
#pragma unroll
    for (int it = 0; it < 8; it++) {
        const int j = t + 256 * it;
        const int c = j >> 5;
        const int q = j & 31;
        const float4* gp = (const float4*)(kan_coeff + c * 256 + q * 8);
        const float4 v0 = gp[0];
        const float4 v1 = gp[1];
        float v[8] = {v0.x, v0.y, v0.z, v0.w, v1.x, v1.y, v1.z, v1.w};
        uint32_t hi[4], lo[4];
#pragma unroll
        for (int k = 0; k < 4; k++) {
            const __nv_bfloat16 h0 = __float2bfloat16_rn(v[2 * k]);
            const __nv_bfloat16 h1 = __float2bfloat16_rn(v[2 * k + 1]);
            const float l0 = v[2 * k]     - __bfloat162float(h0);
            const float l1 = v[2 * k + 1] - __bfloat162float(h1);
            __nv_bfloat162 hh; hh.x = h0; hh.y = h1;
            hi[k] = *reinterpret_cast<uint32_t*>(&hh);
            lo[k] = pack_bf2(l0, l1);
        }
        const uint32_t off = (uint32_t)(c * 512 + ((q ^ (c & 7)) << 4));
        *(uint4*)(smc + OFF_B_HI + off) = make_uint4(hi[0], hi[1], hi[2], hi[3]);
        *(uint4*)(smc + OFF_B_LO + off) = make_uint4(lo[0], lo[1], lo[2], lo[3]);
    }

    // *** R8 BUG FIX: staging is written by all warps but read by producer warps
    // immediately below — must barrier BEFORE the pipeline fill. ***
    __syncthreads();

    // ---- persistent double-buffered pipeline ----
    // warps 0-3: producers (stage-1 -> A tiles); warps 4-7: consumers (MMA+store).
    if (wid < 4) produce_block(smc, X, par, bid, 0, t);
    __syncthreads();

    for (int j = 0;; j++) {
        const int blk  = bid + j * GRID;
        const int nblk = bid + (j + 1) * GRID;
        const int buf  = j & 1;
        if (wid < 4) {
            if (nblk < NBLK) produce_block(smc, X, par, nblk, buf ^ 1, t);
        } else {
            consume_block(smem_base, par, out, blk, buf, wid - 4, lane);
        }
        __syncthreads();
        if (nblk >= NBLK) break;
    }
}

extern "C" void kernel_launch(void* const* d_in, const int* in_sizes, int n_in,
                              void* d_out, int out_size) {
    int iX = 0, iP = 1, iW = 2, iC = 5, iKB = 6;
    int i32[2] = {3, 4};
    int n32 = 0;
    for (int i = 0; i < n_in; i++) {
        switch (in_sizes[i]) {
            case 4194304: iX = i; break;
            case 16:      iP = i; break;
            case 512:     iW = i; break;
            case 16384:   iC = i; break;
            case 64:      iKB = i; break;
            case 32:      if (n32 < 2) i32[n32] = i; n32++; break;
            default: break;
        }
    }

    const float* X      = (const float*)d_in[iX];
    const float* phases = (const float*)d_in[iP];
    const float* w      = (const float*)d_in[iW];
    const float* cand0  = (const float*)d_in[i32[0]];
    const float* cand1  = (const float*)d_in[i32[1]];
    const float* coeff  = (const float*)d_in[iC];
    const float* kbias  = (const float*)d_in[iKB];
    float* out          = (float*)d_out;

    cudaFuncSetAttribute(qkan_pipe_kernel, cudaFuncAttributeMaxDynamicSharedMemorySize,
                         SMEM_TOTAL);
    qkan_pipe_kernel<<<GRID, 256, SMEM_TOTAL>>>(X, phases, w, cand0, cand1,
                                                coeff, kbias, out);
}

// round 11
// speedup vs baseline: 1.1581x; 1.1581x over previous
#include <cuda_runtime.h>
#include <cuda_bf16.h>
#include <cstdint>

#define BATCH  131072
#define FEAT   32
#define DEG    16
#define CLS    64
#define GRIDK  8
#define TBROWS 128          // rows per block
#define NTHR   512          // 16 warps
#define NKT    16           // K=256 / 16 per MMA

// ---- dynamic smem byte offsets ----
#define OFF_FLAG    0
#define OFF_PAR     64                        // float params
#define PAR_WT      0                         // [d][f] 512 floats
#define PAR_INV     512
#define PAR_CP      544
#define PAR_SP      560
#define PAR_SC      576
#define PAR_BI      608
#define PAR_KB      640                       // 64 floats
#define OFF_A_HI    4096                      // [128][256] bf16, 512B rows, chunk^row swizzle
#define OFF_A_LO    (OFF_A_HI + 65536)
#define OFF_B_HI    (OFF_A_LO + 65536)        // [64][256] bf16
#define OFF_B_LO    (OFF_B_HI + 32768)
#define SMEM_TOTAL  (OFF_B_LO + 32768)        // 200704 B

static __device__ __forceinline__ uint32_t smem_u32(const void* p) {
    uint32_t a;
    asm("{ .reg .u64 t; cvta.to.shared.u64 t, %1; cvt.u32.u64 %0, t; }" : "=r"(a) : "l"(p));
    return a;
}
static __device__ __forceinline__ void ldsm4(uint32_t& r0, uint32_t& r1, uint32_t& r2,
                                             uint32_t& r3, uint32_t addr) {
    asm volatile("ldmatrix.sync.aligned.m8n8.x4.shared.b16 {%0,%1,%2,%3}, [%4];"
                 : "=r"(r0), "=r"(r1), "=r"(r2), "=r"(r3) : "r"(addr));
}
static __device__ __forceinline__ void mma_bf16(float* c, const uint32_t* a,
                                                const uint32_t* b) {
    asm volatile("mma.sync.aligned.m16n8k16.row.col.f32.bf16.bf16.f32 "
                 "{%0,%1,%2,%3}, {%4,%5,%6,%7}, {%8,%9}, {%0,%1,%2,%3};"
                 : "+f"(c[0]), "+f"(c[1]), "+f"(c[2]), "+f"(c[3])
                 : "r"(a[0]), "r"(a[1]), "r"(a[2]), "r"(a[3]), "r"(b[0]), "r"(b[1]));
}
static __device__ __forceinline__ uint32_t pack_bf2(float a, float b) {
    __nv_bfloat162 h = __floats2bfloat162_rn(a, b);
    return *reinterpret_cast<uint32_t*>(&h);
}

__global__ __launch_bounds__(NTHR)
void qkan_mma_kernel(const float* __restrict__ X,
                     const float* __restrict__ phases,
                     const float* __restrict__ lcu_w,
                     const float* __restrict__ cand0,
                     const float* __restrict__ cand1,
                     const float* __restrict__ kan_coeff,
                     const float* __restrict__ kan_bias,
                     float* __restrict__ out) {
    extern __shared__ char smc[];
    float* par = (float*)(smc + OFF_PAR);

    const int t    = threadIdx.x;
    const int wid  = t >> 5;
    const int lane = t & 31;
    const int row0 = blockIdx.x * TBROWS;
    const uint32_t smem_base = smem_u32(smc);
    const float CLIPF = (float)(1.0 - 1e-6);

    // ---- scale/bias disambiguation (scale mean ~1 > bias mean ~0) ----
    if (t == 0) {
        float s0 = 0.f, s1 = 0.f;
        for (int i = 0; i < 32; i++) { s0 += cand0[i]; s1 += cand1[i]; }
        *(int*)(smc + OFF_FLAG) = (s0 > s1) ? 1 : 0;
    }
    __syncthreads();
    const int flag = *(const int*)(smc + OFF_FLAG);

    // ---- parameter staging (cooperatively written) ----
    for (int j = t; j < DEG * FEAT; j += NTHR) {       // lcu_w [f][d] -> wT [d][f]
        const int f = j >> 4, d = j & 15;
        par[PAR_WT + d * 32 + f] = lcu_w[j];
    }
    if (t < 32) {
        float denom = 1e-6f;
#pragma unroll
        for (int d = 0; d < DEG; d++) denom += fabsf(lcu_w[t * DEG + d]);
        par[PAR_INV + t] = 1.0f / denom;
        par[PAR_SC + t] = flag ? cand0[t] : cand1[t];
        par[PAR_BI + t] = flag ? cand1[t] : cand0[t];
    }
    if (t < 16) {
        float sv, cv;
        sincosf(phases[t], &sv, &cv);
        par[PAR_CP + t] = cv;
        par[PAR_SP + t] = sv;
    }
    if (t < 64) par[PAR_KB + t] = kan_bias[t];

    // ---- B tiles: kan_coeff [c][256] -> bf16 hi/lo, 512B rows, chunk^(c&7) swizzle ----
#pragma unroll
    for (int it = 0; it < 4; it++) {
        const int j = t + NTHR * it;         // 2048 chunks of 8 floats
        const int c = j >> 5;                // class row 0..63
        const int q = j & 31;                // 16B chunk within row
        const float4* gp = (const float4*)(kan_coeff + c * 256 + q * 8);
        const float4 v0 = gp[0];
        const float4 v1 = gp[1];
        float v[8] = {v0.x, v0.y, v0.z, v0.w, v1.x, v1.y, v1.z, v1.w};
        uint32_t hi[4], lo[4];
#pragma unroll
        for (int k = 0; k < 4; k++) {
            const __nv_bfloat16 h0 = __float2bfloat16_rn(v[2 * k]);
            const __nv_bfloat16 h1 = __float2bfloat16_rn(v[2 * k + 1]);
            const float l0 = v[2 * k]     - __bfloat162float(h0);
            const float l1 = v[2 * k + 1] - __bfloat162float(h1);
            __nv_bfloat162 hh; hh.x = h0; hh.y = h1;
            hi[k] = *reinterpret_cast<uint32_t*>(&hh);
            lo[k] = pack_bf2(l0, l1);
        }
        const uint32_t off = (uint32_t)(c * 512 + ((q ^ (c & 7)) << 4));
        *(uint4*)(smc + OFF_B_HI + off) = make_uint4(hi[0], hi[1], hi[2], hi[3]);
        *(uint4*)(smc + OFF_B_LO + off) = make_uint4(lo[0], lo[1], lo[2], lo[3]);
    }

    // *** RACE FIX (R10 bug): params are cooperatively written above and read by
    // stage-1 below across warps — barrier required. ***
    __syncthreads();

    // ---- stage 1 (verified R4 math) + Chebyshev basis -> A hi/lo bf16 tiles ----
    {
        const int f   = t & 31;
        const int w16 = t >> 5;              // 0..15
        const float invd = par[PAR_INV + f];
        const float sc   = par[PAR_SC + f];
        const float bi   = par[PAR_BI + f];
#pragma unroll 2
        for (int i = 0; i < TBROWS / 16; i++) {
            const int r = w16 + 16 * i;
            float x = X[(size_t)(row0 + r) * FEAT + f];
            x = fminf(fmaxf(x, -CLIPF), CLIPF);
            const float sn = sqrtf(fmaf(-x, x, 1.0f));
            float c = x, s = sn, num = 0.f;
#pragma unroll
            for (int d = 0; d < DEG; d++) {
                const float q = fmaf(c, par[PAR_CP + d], -(s * par[PAR_SP + d]));
                num = fmaf(par[PAR_WT + d * 32 + f], q, num);
                const float cn = fmaf(-sn, s, c * x);
                s = fmaf(sn, c, s * x);
                c = cn;
            }
            float y = tanhf(fmaf(sc, num * invd, bi));
            y = fminf(fmaxf(y, -CLIPF), CLIPF);

            float T[GRIDK];
            T[0] = 1.0f; T[1] = y;
            const float y2 = y + y;
#pragma unroll
            for (int k = 2; k < GRIDK; k++) T[k] = fmaf(y2, T[k - 1], -T[k - 2]);

            uint32_t hi[4], lo[4];
#pragma unroll
            for (int k = 0; k < 4; k++) {
                const __nv_bfloat16 h0 = __float2bfloat16_rn(T[2 * k]);
                const __nv_bfloat16 h1 = __float2bfloat16_rn(T[2 * k + 1]);
                const float l0 = T[2 * k]     - __bfloat162float(h0);
                const float l1 = T[2 * k + 1] - __bfloat162float(h1);
                __nv_bfloat162 hh; hh.x = h0; hh.y = h1;
                hi[k] = *reinterpret_cast<uint32_t*>(&hh);
                lo[k] = pack_bf2(l0, l1);
            }
            const uint32_t off = (uint32_t)(r * 512 + ((f ^ (r & 7)) << 4));
            *(uint4*)(smc + OFF_A_HI + off) = make_uint4(hi[0], hi[1], hi[2], hi[3]);
            *(uint4*)(smc + OFF_A_LO + off) = make_uint4(lo[0], lo[1], lo[2], lo[3]);
        }
    }
    __syncthreads();

    // ---- MMA phase: warp -> (m-tile wid>>1: rows *16, class-half wid&1: 32 classes) ----
    {
        const int mt    = wid >> 1;                              // 0..7
        const int nhalf = wid & 1;                               // 0..1
        const int lr   = lane & 7;
        const int a_cb = (lane >> 4) & 1;
        const int arow = mt * 16 + ((lane >> 3) & 1) * 8 + lr;
        const int b_cb = (lane >> 3) & 1;
        const int bn   = ((lane >> 4) & 1) * 8 + lr;

        const uint32_t aBaseHi = smem_base + OFF_A_HI + arow * 512;
        const uint32_t aBaseLo = smem_base + OFF_A_LO + arow * 512;
        uint32_t bBaseHi[2];
#pragma unroll
        for (int p = 0; p < 2; p++)
            bBaseHi[p] = smem_base + OFF_B_HI + ((nhalf * 2 + p) * 16 + bn) * 512;

        float C[4][4];
#pragma unroll
        for (int n = 0; n < 4; n++)
#pragma unroll
            for (int j = 0; j < 4; j++) C[n][j] = 0.f;

#pragma unroll
        for (int kt = 0; kt < NKT; kt++) {
            const uint32_t offA = (uint32_t)(((kt * 2 + a_cb) ^ lr) << 4);
            const uint32_t offB = (uint32_t)(((kt * 2 + b_cb) ^ lr) << 4);
            uint32_t ah[4], al[4];
            ldsm4(ah[0], ah[1], ah[2], ah[3], aBaseHi + offA);
            ldsm4(al[0], al[1], al[2], al[3], aBaseLo + offA);
            uint32_t bh[4][2], bl[4][2];
#pragma unroll
            for (int p = 0; p < 2; p++) {
                ldsm4(bh[2 * p][0], bh[2 * p][1], bh[2 * p + 1][0], bh[2 * p + 1][1],
                      bBaseHi[p] + offB);
                ldsm4(bl[2 * p][0], bl[2 * p][1], bl[2 * p + 1][0], bl[2 * p + 1][1],
                      bBaseHi[p] + 32768u + offB);
            }
#pragma unroll
            for (int n = 0; n < 4; n++) {
                mma_bf16(C[n], ah, bh[n]);
                mma_bf16(C[n], al, bh[n]);
                mma_bf16(C[n], ah, bl[n]);
            }
        }

        // ---- epilogue: + kan_bias, float2 stores ----
        const int qrow = lane >> 2;            // 0..7
        const int col2 = 2 * (lane & 3);       // 0,2,4,6
        const int gr0 = row0 + mt * 16 + qrow;
#pragma unroll
        for (int n = 0; n < 4; n++) {
            const int col = nhalf * 32 + n * 8 + col2;
            const float kb0 = par[PAR_KB + col];
            const float kb1 = par[PAR_KB + col + 1];
            float2 v0, v1;
            v0.x = C[n][0] + kb0; v0.y = C[n][1] + kb1;
            v1.x = C[n][2] + kb0; v1.y = C[n][3] + kb1;
            *(float2*)(out + (size_t)gr0 * CLS + col) = v0;
            *(float2*)(out + (size_t)(gr0 + 8) * CLS + col) = v1;
        }
    }
}

extern "C" void kernel_launch(void* const* d_in, const int* in_sizes, int n_in,
                              void* d_out, int out_size) {
    int iX = 0, iP = 1, iW = 2, iC = 5, iKB = 6;
    int i32[2] = {3, 4};
    int n32 = 0;
    for (int i = 0; i < n_in; i++) {
        switch (in_sizes[i]) {
            case 4194304: iX = i; break;
            case 16:      iP = i; break;
            case 512:     iW = i; break;
            case 16384:   iC = i; break;
            case 64:      iKB = i; break;
            case 32:      if (n32 < 2) i32[n32] = i; n32++; break;
            default: break;
        }
    }

    const float* X      = (const float*)d_in[iX];
    const float* phases = (const float*)d_in[iP];
    const float* w      = (const float*)d_in[iW];
    const float* cand0  = (const float*)d_in[i32[0]];
    const float* cand1  = (const float*)d_in[i32[1]];
    const float* coeff  = (const float*)d_in[iC];
    const float* kbias  = (const float*)d_in[iKB];
    float* out          = (float*)d_out;

    cudaFuncSetAttribute(qkan_mma_kernel, cudaFuncAttributeMaxDynamicSharedMemorySize,
                         SMEM_TOTAL);
    qkan_mma_kernel<<<BATCH / TBROWS, NTHR, SMEM_TOTAL>>>(X, phases, w, cand0, cand1,
                                                          coeff, kbias, out);
}

// round 12
// speedup vs baseline: 1.1904x; 1.0279x over previous
#include <cuda_runtime.h>
#include <cuda_bf16.h>
#include <cstdint>

#define BATCH  131072
#define FEAT   32
#define DEG    16
#define CLS    64
#define GRIDK  8
#define TBROWS 128          // rows per block
#define NTHR   512          // 16 warps
#define NKT    16           // K=256 / 16 per MMA

// ---- dynamic smem byte offsets ----
#define OFF_FLAG    0
#define OFF_PAR     64                        // float params
#define PAR_WT      0                         // [d][f] 512 floats
#define PAR_INV     512
#define PAR_CP      544
#define PAR_SP      560
#define PAR_SC      576
#define PAR_BI      608
#define PAR_KB      640                       // 64 floats
#define OFF_A_HI    4096                      // [128][256] bf16, 512B rows, chunk^row swizzle
#define OFF_A_LO    (OFF_A_HI + 65536)
#define OFF_B_HI    (OFF_A_LO + 65536)        // [64][256] bf16
#define OFF_B_LO    (OFF_B_HI + 32768)
#define SMEM_TOTAL  (OFF_B_LO + 32768)        // 200704 B

static __device__ __forceinline__ uint32_t smem_u32(const void* p) {
    uint32_t a;
    asm("{ .reg .u64 t; cvta.to.shared.u64 t, %1; cvt.u32.u64 %0, t; }" : "=r"(a) : "l"(p));
    return a;
}
static __device__ __forceinline__ void ldsm4(uint32_t& r0, uint32_t& r1, uint32_t& r2,
                                             uint32_t& r3, uint32_t addr) {
    asm volatile("ldmatrix.sync.aligned.m8n8.x4.shared.b16 {%0,%1,%2,%3}, [%4];"
                 : "=r"(r0), "=r"(r1), "=r"(r2), "=r"(r3) : "r"(addr));
}
static __device__ __forceinline__ void mma_bf16(float* c, const uint32_t* a,
                                                const uint32_t* b) {
    asm volatile("mma.sync.aligned.m16n8k16.row.col.f32.bf16.bf16.f32 "
                 "{%0,%1,%2,%3}, {%4,%5,%6,%7}, {%8,%9}, {%0,%1,%2,%3};"
                 : "+f"(c[0]), "+f"(c[1]), "+f"(c[2]), "+f"(c[3])
                 : "r"(a[0]), "r"(a[1]), "r"(a[2]), "r"(a[3]), "r"(b[0]), "r"(b[1]));
}
// fast tanh: (e^2x - 1)/(e^2x + 1); arg bounded (|sc*lcu+bi| <~ 2.5) so no overflow.
static __device__ __forceinline__ float tanh_fast(float x) {
    const float e2x = exp2f(x * 2.8853900817779268f);   // e^(2x)
    return (e2x - 1.0f) * __frcp_rn(e2x + 1.0f);
}
// split pair (f0,f1) -> bf16x2 hi + bf16x2 lo
static __device__ __forceinline__ void split_pair(float f0, float f1,
                                                  uint32_t& hi, uint32_t& lo) {
    const __nv_bfloat162 h = __floats2bfloat162_rn(f0, f1);
    hi = *reinterpret_cast<const uint32_t*>(&h);
    const float h0 = __uint_as_float(hi << 16);          // low bf16 -> f32
    const float h1 = __uint_as_float(hi & 0xFFFF0000u);  // high bf16 -> f32
    const __nv_bfloat162 l = __floats2bfloat162_rn(f0 - h0, f1 - h1);
    lo = *reinterpret_cast<const uint32_t*>(&l);
}

__global__ __launch_bounds__(NTHR)
void qkan_mma_kernel(const float* __restrict__ X,
                     const float* __restrict__ phases,
                     const float* __restrict__ lcu_w,
                     const float* __restrict__ cand0,
                     const float* __restrict__ cand1,
                     const float* __restrict__ kan_coeff,
                     const float* __restrict__ kan_bias,
                     float* __restrict__ out) {
    extern __shared__ char smc[];
    float* par = (float*)(smc + OFF_PAR);

    const int t    = threadIdx.x;
    const int wid  = t >> 5;
    const int lane = t & 31;
    const int row0 = blockIdx.x * TBROWS;
    const uint32_t smem_base = smem_u32(smc);
    const float CLIPF = (float)(1.0 - 1e-6);

    // ---- scale/bias disambiguation (scale mean ~1 > bias mean ~0) ----
    if (t == 0) {
        float s0 = 0.f, s1 = 0.f;
        for (int i = 0; i < 32; i++) { s0 += cand0[i]; s1 += cand1[i]; }
        *(int*)(smc + OFF_FLAG) = (s0 > s1) ? 1 : 0;
    }
    __syncthreads();
    const int flag = *(const int*)(smc + OFF_FLAG);

    // ---- parameter staging (cooperatively written) ----
    for (int j = t; j < DEG * FEAT; j += NTHR) {       // lcu_w [f][d] -> wT [d][f]
        const int f = j >> 4, d = j & 15;
        par[PAR_WT + d * 32 + f] = lcu_w[j];
    }
    if (t < 32) {
        float denom = 1e-6f;
#pragma unroll
        for (int d = 0; d < DEG; d++) denom += fabsf(lcu_w[t * DEG + d]);
        par[PAR_INV + t] = 1.0f / denom;
        par[PAR_SC + t] = flag ? cand0[t] : cand1[t];
        par[PAR_BI + t] = flag ? cand1[t] : cand0[t];
    }
    if (t < 16) {
        float sv, cv;
        sincosf(phases[t], &sv, &cv);
        par[PAR_CP + t] = cv;
        par[PAR_SP + t] = sv;
    }
    if (t < 64) par[PAR_KB + t] = kan_bias[t];

    // ---- B tiles: kan_coeff [c][256] -> bf16 hi/lo, 512B rows, chunk^(c&7) swizzle ----
#pragma unroll
    for (int it = 0; it < 4; it++) {
        const int j = t + NTHR * it;         // 2048 chunks of 8 floats
        const int c = j >> 5;                // class row 0..63
        const int q = j & 31;                // 16B chunk within row
        const float4* gp = (const float4*)(kan_coeff + c * 256 + q * 8);
        const float4 v0 = gp[0];
        const float4 v1 = gp[1];
        uint32_t hi[4], lo[4];
        split_pair(v0.x, v0.y, hi[0], lo[0]);
        split_pair(v0.z, v0.w, hi[1], lo[1]);
        split_pair(v1.x, v1.y, hi[2], lo[2]);
        split_pair(v1.z, v1.w, hi[3], lo[3]);
        const uint32_t off = (uint32_t)(c * 512 + ((q ^ (c & 7)) << 4));
        *(uint4*)(smc + OFF_B_HI + off) = make_uint4(hi[0], hi[1], hi[2], hi[3]);
        *(uint4*)(smc + OFF_B_LO + off) = make_uint4(lo[0], lo[1], lo[2], lo[3]);
    }

    // params cooperatively written above, read by stage-1 below: barrier required.
    __syncthreads();

    // ---- stage 1 (verified R4 math) + Chebyshev basis -> A hi/lo bf16 tiles ----
    {
        const int f   = t & 31;
        const int w16 = t >> 5;              // 0..15
        const float invd = par[PAR_INV + f];
        const float sc   = par[PAR_SC + f];
        const float bi   = par[PAR_BI + f];
#pragma unroll 2
        for (int i = 0; i < TBROWS / 16; i++) {
            const int r = w16 + 16 * i;
            float x = X[(size_t)(row0 + r) * FEAT + f];
            x = fminf(fmaxf(x, -CLIPF), CLIPF);
            const float sn = sqrtf(fmaf(-x, x, 1.0f));
            float c = x, s = sn, num = 0.f;
#pragma unroll
            for (int d = 0; d < DEG; d++) {
                const float q = fmaf(c, par[PAR_CP + d], -(s * par[PAR_SP + d]));
                num = fmaf(par[PAR_WT + d * 32 + f], q, num);
                const float cn = fmaf(-sn, s, c * x);
                s = fmaf(sn, c, s * x);
                c = cn;
            }
            float y = tanh_fast(fmaf(sc, num * invd, bi));
            y = fminf(fmaxf(y, -CLIPF), CLIPF);

            float T[GRIDK];
            T[0] = 1.0f; T[1] = y;
            const float y2 = y + y;
#pragma unroll
            for (int k = 2; k < GRIDK; k++) T[k] = fmaf(y2, T[k - 1], -T[k - 2]);

            uint32_t hi[4], lo[4];
            split_pair(T[0], T[1], hi[0], lo[0]);
            split_pair(T[2], T[3], hi[1], lo[1]);
            split_pair(T[4], T[5], hi[2], lo[2]);
            split_pair(T[6], T[7], hi[3], lo[3]);
            const uint32_t off = (uint32_t)(r * 512 + ((f ^ (r & 7)) << 4));
            *(uint4*)(smc + OFF_A_HI + off) = make_uint4(hi[0], hi[1], hi[2], hi[3]);
            *(uint4*)(smc + OFF_A_LO + off) = make_uint4(lo[0], lo[1], lo[2], lo[3]);
        }
    }
    __syncthreads();

    // ---- MMA phase: 8 warps, warp tile m32 x n32 (mt = wid>>1, nhalf = wid&1) ----
    if (wid < 8) {
        const int mt    = wid >> 1;                              // 0..3 -> rows mt*32..+31
        const int nhalf = wid & 1;                               // 0..1 -> cols nhalf*32..+31
        const int lr   = lane & 7;
        const int a_cb = (lane >> 4) & 1;
        const int ar0  = mt * 32 + ((lane >> 3) & 1) * 8 + lr;   // m16 tile 0 row
        const int b_cb = (lane >> 3) & 1;
        const int bn   = ((lane >> 4) & 1) * 8 + lr;

        const uint32_t aHi0 = smem_base + OFF_A_HI + ar0 * 512;
        const uint32_t aHi1 = aHi0 + 16 * 512;                   // m16 tile 1 (+16 rows)
        const uint32_t aLo0 = smem_base + OFF_A_LO + ar0 * 512;
        const uint32_t aLo1 = aLo0 + 16 * 512;
        uint32_t bBaseHi[2];
#pragma unroll
        for (int p = 0; p < 2; p++)
            bBaseHi[p] = smem_base + OFF_B_HI + ((nhalf * 2 + p) * 16 + bn) * 512;

        float C[2][4][4];
#pragma unroll
        for (int m = 0; m < 2; m++)
#pragma unroll
            for (int n = 0; n < 4; n++)
#pragma unroll
                for (int j = 0; j < 4; j++) C[m][n][j] = 0.f;

#pragma unroll
        for (int kt = 0; kt < NKT; kt++) {
            const uint32_t offA = (uint32_t)(((kt * 2 + a_cb) ^ lr) << 4);
            const uint32_t offB = (uint32_t)(((kt * 2 + b_cb) ^ lr) << 4);
            uint32_t ah[2][4], al[2][4];
            ldsm4(ah[0][0], ah[0][1], ah[0][2], ah[0][3], aHi0 + offA);
            ldsm4(ah[1][0], ah[1][1], ah[1][2], ah[1][3], aHi1 + offA);
            ldsm4(al[0][0], al[0][1], al[0][2], al[0][3], aLo0 + offA);
            ldsm4(al[1][0], al[1][1], al[1][2], al[1][3], aLo1 + offA);
            uint32_t bh[4][2], bl[4][2];
#pragma unroll
            for (int p = 0; p < 2; p++) {
                ldsm4(bh[2 * p][0], bh[2 * p][1], bh[2 * p + 1][0], bh[2 * p + 1][1],
                      bBaseHi[p] + offB);
                ldsm4(bl[2 * p][0], bl[2 * p][1], bl[2 * p + 1][0], bl[2 * p + 1][1],
                      bBaseHi[p] + 32768u + offB);
            }
#pragma unroll
            for (int m = 0; m < 2; m++)
#pragma unroll
                for (int n = 0; n < 4; n++) {
                    mma_bf16(C[m][n], ah[m], bh[n]);
                    mma_bf16(C[m][n], al[m], bh[n]);
                    mma_bf16(C[m][n], ah[m], bl[n]);
                }
        }

        // ---- epilogue: + kan_bias, float2 stores ----
        const int qrow = lane >> 2;            // 0..7
        const int col2 = 2 * (lane & 3);       // 0,2,4,6
#pragma unroll
        for (int m = 0; m < 2; m++) {
            const int gr0 = row0 + mt * 32 + m * 16 + qrow;
#pragma unroll
            for (int n = 0; n < 4; n++) {
                const int col = nhalf * 32 + n * 8 + col2;
                const float kb0 = par[PAR_KB + col];
                const float kb1 = par[PAR_KB + col + 1];
                float2 v0, v1;
                v0.x = C[m][n][0] + kb0; v0.y = C[m][n][1] + kb1;
                v1.x = C[m][n][2] + kb0; v1.y = C[m][n][3] + kb1;
                *(float2*)(out + (size_t)gr0 * CLS + col) = v0;
                *(float2*)(out + (size_t)(gr0 + 8) * CLS + col) = v1;
            }
        }
    }
}

extern "C" void kernel_launch(void* const* d_in, const int* in_sizes, int n_in,
                              void* d_out, int out_size) {
    int iX = 0, iP = 1, iW = 2, iC = 5, iKB = 6;
    int i32[2] = {3, 4};
    int n32 = 0;
    for (int i = 0; i < n_in; i++) {
        switch (in_sizes[i]) {
            case 4194304: iX = i; break;
            case 16:      iP = i; break;
            case 512:     iW = i; break;
            case 16384:   iC = i; break;
            case 64:      iKB = i; break;
            case 32:      if (n32 < 2) i32[n32] = i; n32++; break;
            default: break;
        }
    }

    const float* X      = (const float*)d_in[iX];
    const float* phases = (const float*)d_in[iP];
    const float* w      = (const float*)d_in[iW];
    const float* cand0  = (const float*)d_in[i32[0]];
    const float* cand1  = (const float*)d_in[i32[1]];
    const float* coeff  = (const float*)d_in[iC];
    const float* kbias  = (const float*)d_in[iKB];
    float* out          = (float*)d_out;

    cudaFuncSetAttribute(qkan_mma_kernel, cudaFuncAttributeMaxDynamicSharedMemorySize,
                         SMEM_TOTAL);
    qkan_mma_kernel<<<BATCH / TBROWS, NTHR, SMEM_TOTAL>>>(X, phases, w, cand0, cand1,
                                                          coeff, kbias, out);
}